// round 4
// baseline (speedup 1.0000x reference)
#include <cuda_runtime.h>
#include <cstdint>

// Problem constants
#define BB 8
#define TT 2048
#define DD 1024
#define QD 128
#define NEGV -1000000000.0f

// Scratch for q, k, v projections (8*2048*128 fp32 each = 8 MB each)
__device__ float g_q[BB * TT * QD];
__device__ float g_k[BB * TT * QD];
__device__ float g_v[BB * TT * QD];
// Canonical fp32 mask (1.0 = keep, 0.0 = masked) + detected dtype kind
__device__ float g_mask[BB * TT];
__device__ int   g_mask_kind;   // 0 = int32, 1 = uint8, 2 = float32

// ---------------------------------------------------------------------------
// Mask dtype sniffer: the harness ships jnp.bool_ as one of uint8/int32/f32.
//   int32 one  = 01 00 00 00   -> bytes @+1 always 0, @+3 always 0
//   f32   one  = 00 00 80 3F   -> bytes @+1 always 0, @+3 = 0x3F when set
//   uint8 data = random 0/1 at every byte -> byte @+1 nonzero somewhere
// So: any nonzero byte at offset%4==1 => uint8; else any nonzero at
// offset%4==3 => float32; else int32. Single CTA, reads exactly 16384 bytes
// (the smallest possible size for any of the three interpretations).
// ---------------------------------------------------------------------------
__global__ void mask_sniff(const uint8_t* __restrict__ m)
{
    __shared__ unsigned r1[256], r3[256];
    unsigned o1 = 0, o3 = 0;
    const uint32_t* w = (const uint32_t*)m;
    for (int i = threadIdx.x; i < (BB * TT) / 4; i += 256) {
        uint32_t v = w[i];
        o1 |= (v >> 8)  & 0xFFu;   // byte offset 1
        o3 |= (v >> 24) & 0xFFu;   // byte offset 3
    }
    r1[threadIdx.x] = o1; r3[threadIdx.x] = o3;
    __syncthreads();
    for (int s = 128; s; s >>= 1) {
        if (threadIdx.x < s) {
            r1[threadIdx.x] |= r1[threadIdx.x + s];
            r3[threadIdx.x] |= r3[threadIdx.x + s];
        }
        __syncthreads();
    }
    if (threadIdx.x == 0)
        g_mask_kind = r1[0] ? 1 : (r3[0] ? 2 : 0);
}

__global__ void mask_expand(const void* __restrict__ m)
{
    int s = blockIdx.x * 256 + threadIdx.x;
    if (s >= BB * TT) return;
    int kind = g_mask_kind;
    float v;
    if (kind == 1)      v = ((const uint8_t*)m)[s] ? 1.0f : 0.0f;
    else if (kind == 2) v = (((const float*)m)[s] != 0.0f) ? 1.0f : 0.0f;
    else                v = ((const int*)m)[s] ? 1.0f : 0.0f;
    g_mask[s] = v;
}

// ---------------------------------------------------------------------------
// Kernel 1: fused projection GEMM.
//   out[M=B*T, 128] = x[M, 1024] @ W^T   for W in {Wq, Wk, Wv}
// Tile: 64(M) x 64(N), BK=16, 256 threads, 4x4 per-thread microtile.
// ---------------------------------------------------------------------------
__global__ __launch_bounds__(256) void proj_kernel(
    const float* __restrict__ x,
    const float* __restrict__ Wq,
    const float* __restrict__ Wk,
    const float* __restrict__ Wv)
{
    __shared__ float As[16][64];   // As[k][m]
    __shared__ float Bs[16][64];   // Bs[k][n]

    const int m0 = blockIdx.x * 64;
    const int n0 = blockIdx.y * 64;
    const int z  = blockIdx.z;
    const float* __restrict__ W = (z == 0) ? Wq : ((z == 1) ? Wk : Wv);
    float* __restrict__ outp    = (z == 0) ? g_q : ((z == 1) ? g_k : g_v);

    const int tid  = threadIdx.x;
    const int ty   = tid >> 4;         // 0..15
    const int tx   = tid & 15;         // 0..15
    const int lrow = tid >> 2;         // 0..63
    const int lk   = (tid & 3) << 2;   // 0,4,8,12

    const float* xg = x + (size_t)(m0 + lrow) * DD + lk;
    const float* wg = W + (size_t)(n0 + lrow) * DD + lk;

    float acc[4][4] = {};

    for (int k0 = 0; k0 < DD; k0 += 16) {
        float4 a = *(const float4*)(xg + k0);
        float4 b = *(const float4*)(wg + k0);
        As[lk + 0][lrow] = a.x; As[lk + 1][lrow] = a.y;
        As[lk + 2][lrow] = a.z; As[lk + 3][lrow] = a.w;
        Bs[lk + 0][lrow] = b.x; Bs[lk + 1][lrow] = b.y;
        Bs[lk + 2][lrow] = b.z; Bs[lk + 3][lrow] = b.w;
        __syncthreads();
        #pragma unroll
        for (int kk = 0; kk < 16; kk++) {
            float4 av = *(const float4*)&As[kk][ty << 2];
            float4 bv = *(const float4*)&Bs[kk][tx << 2];
            float aa[4] = {av.x, av.y, av.z, av.w};
            float bb[4] = {bv.x, bv.y, bv.z, bv.w};
            #pragma unroll
            for (int i = 0; i < 4; i++)
                #pragma unroll
                for (int j = 0; j < 4; j++)
                    acc[i][j] = fmaf(aa[i], bb[j], acc[i][j]);
        }
        __syncthreads();
    }

    #pragma unroll
    for (int i = 0; i < 4; i++) {
        float4 v = make_float4(acc[i][0], acc[i][1], acc[i][2], acc[i][3]);
        *(float4*)&outp[(size_t)(m0 + (ty << 2) + i) * QD + n0 + (tx << 2)] = v;
    }
}

// ---------------------------------------------------------------------------
// Kernel 2: flash attention with key-position mask.
// One CTA handles 64 query rows of one batch; loops over all 2048 keys in
// 64-row tiles with online softmax. 256 threads.
// ---------------------------------------------------------------------------
#define ATTN_SMEM_FLOATS (128*64 + 128*64 + 64*128 + 64*64 + 5*64)
#define ATTN_SMEM_BYTES  (ATTN_SMEM_FLOATS * 4)

__global__ __launch_bounds__(256) void attn_kernel(float* __restrict__ out)
{
    extern __shared__ float sm[];
    float* Qs       = sm;                 // [128][64]  Qs[d][q]
    float* Ks       = Qs + 128 * 64;      // [128][64]  Ks[d][s]
    float* Vs       = Ks + 128 * 64;      // [64][128]  Vs[s][d]
    float* Ps       = Vs + 64 * 128;      // [64][64]   Ps[s][q]
    float* sm_m     = Ps + 64 * 64;       // running max  [64]
    float* sm_sum   = sm_m + 64;          // running sum  [64]
    float* sm_scale = sm_sum + 64;        // rescale      [64]
    float* sm_rmax  = sm_scale + 64;      // tile rowmax  [64]
    float* mk       = sm_rmax + 64;       // mask tile    [64]

    const int tid = threadIdx.x;
    const int b   = blockIdx.y;
    const int t0  = blockIdx.x * 64;
    const int ty  = tid >> 4;   // 0..15
    const int tx  = tid & 15;   // 0..15

    // Load Q tile (64 x 128), transposed into Qs[d][q]
    {
        const float* qg = g_q + (size_t)(b * TT + t0) * QD;
        #pragma unroll
        for (int r = 0; r < 8; r++) {
            int idx = tid + r * 256;          // float4 index, 0..2047
            int row = idx >> 5;               // 0..63
            int dq  = (idx & 31) << 2;        // 0..124
            float4 v = *(const float4*)(qg + row * QD + dq);
            Qs[(dq + 0) * 64 + row] = v.x; Qs[(dq + 1) * 64 + row] = v.y;
            Qs[(dq + 2) * 64 + row] = v.z; Qs[(dq + 3) * 64 + row] = v.w;
        }
    }
    if (tid < 64) { sm_m[tid] = -3.0e38f; sm_sum[tid] = 0.0f; }

    float acc[4][8] = {};

    const float* mg = g_mask + b * TT;
    const float* kg = g_k + (size_t)(b * TT) * QD;
    const float* vg = g_v + (size_t)(b * TT) * QD;

    for (int s0 = 0; s0 < TT; s0 += 64) {
        __syncthreads();  // protect smem from previous iteration / Q load
        if (tid < 64) mk[tid] = mg[s0 + tid];
        #pragma unroll
        for (int r = 0; r < 8; r++) {
            int idx = tid + r * 256;
            int row = idx >> 5;
            int dq  = (idx & 31) << 2;
            float4 kv = *(const float4*)(kg + (s0 + row) * QD + dq);
            Ks[(dq + 0) * 64 + row] = kv.x; Ks[(dq + 1) * 64 + row] = kv.y;
            Ks[(dq + 2) * 64 + row] = kv.z; Ks[(dq + 3) * 64 + row] = kv.w;
            float4 vv = *(const float4*)(vg + (s0 + row) * QD + dq);
            *(float4*)&Vs[row * 128 + dq] = vv;
        }
        __syncthreads();

        // GEMM1: logits[4q][4s] = Q . K^T over d=128
        float l[4][4] = {};
        #pragma unroll 8
        for (int d = 0; d < 128; d++) {
            float4 a  = *(const float4*)&Qs[d * 64 + (ty << 2)];
            float4 bq = *(const float4*)&Ks[d * 64 + (tx << 2)];
            float aa[4] = {a.x, a.y, a.z, a.w};
            float bb[4] = {bq.x, bq.y, bq.z, bq.w};
            #pragma unroll
            for (int i = 0; i < 4; i++)
                #pragma unroll
                for (int j = 0; j < 4; j++)
                    l[i][j] = fmaf(aa[i], bb[j], l[i][j]);
        }

        // Mask + per-tile row max
        float mkj[4];
        #pragma unroll
        for (int j = 0; j < 4; j++) mkj[j] = mk[(tx << 2) + j];
        float rm[4];
        #pragma unroll
        for (int i = 0; i < 4; i++) {
            #pragma unroll
            for (int j = 0; j < 4; j++)
                l[i][j] = (mkj[j] != 0.0f) ? l[i][j] : NEGV;
            rm[i] = fmaxf(fmaxf(l[i][0], l[i][1]), fmaxf(l[i][2], l[i][3]));
        }
        #pragma unroll
        for (int i = 0; i < 4; i++) {
            #pragma unroll
            for (int off = 8; off; off >>= 1)
                rm[i] = fmaxf(rm[i], __shfl_xor_sync(0xffffffffu, rm[i], off));
        }
        if (tx == 0) {
            #pragma unroll
            for (int i = 0; i < 4; i++) sm_rmax[(ty << 2) + i] = rm[i];
        }
        __syncthreads();

        // Online softmax state update (one thread per row)
        if (tid < 64) {
            float mo = sm_m[tid];
            float mn = fmaxf(mo, sm_rmax[tid]);
            float sc = __expf(mo - mn);
            sm_scale[tid] = sc;
            sm_m[tid]     = mn;
            sm_sum[tid]  *= sc;
        }
        __syncthreads();

        // p = exp(l - m_new), write Ps[s][q], accumulate row sums
        float rs[4];
        #pragma unroll
        for (int i = 0; i < 4; i++) {
            int row = (ty << 2) + i;
            float mn = sm_m[row];
            float p[4];
            #pragma unroll
            for (int j = 0; j < 4; j++) {
                p[j] = (mkj[j] != 0.0f) ? __expf(l[i][j] - mn) : 0.0f;
                Ps[((tx << 2) + j) * 64 + row] = p[j];
            }
            rs[i] = (p[0] + p[1]) + (p[2] + p[3]);
        }
        #pragma unroll
        for (int i = 0; i < 4; i++) {
            #pragma unroll
            for (int off = 8; off; off >>= 1)
                rs[i] += __shfl_xor_sync(0xffffffffu, rs[i], off);
        }
        if (tx == 0) {
            #pragma unroll
            for (int i = 0; i < 4; i++) sm_sum[(ty << 2) + i] += rs[i];
        }
        // Rescale accumulator (same ty->row mapping as GEMM2)
        #pragma unroll
        for (int i = 0; i < 4; i++) {
            float sc = sm_scale[(ty << 2) + i];
            #pragma unroll
            for (int j = 0; j < 8; j++) acc[i][j] *= sc;
        }
        __syncthreads();  // Ps fully written

        // GEMM2: acc[4q][8d] += P[64q][64s] @ V[64s][128d]
        #pragma unroll 4
        for (int ss = 0; ss < 64; ss++) {
            float4 a  = *(const float4*)&Ps[ss * 64 + (ty << 2)];
            float4 b0 = *(const float4*)&Vs[ss * 128 + (tx << 3)];
            float4 b1 = *(const float4*)&Vs[ss * 128 + (tx << 3) + 4];
            float aa[4] = {a.x, a.y, a.z, a.w};
            float bb[8] = {b0.x, b0.y, b0.z, b0.w, b1.x, b1.y, b1.z, b1.w};
            #pragma unroll
            for (int i = 0; i < 4; i++)
                #pragma unroll
                for (int j = 0; j < 8; j++)
                    acc[i][j] = fmaf(aa[i], bb[j], acc[i][j]);
        }
    }
    __syncthreads();

    // Final normalize + store
    #pragma unroll
    for (int i = 0; i < 4; i++) {
        int row = (ty << 2) + i;
        float inv = 1.0f / sm_sum[row];
        float4 o0 = make_float4(acc[i][0] * inv, acc[i][1] * inv,
                                acc[i][2] * inv, acc[i][3] * inv);
        float4 o1 = make_float4(acc[i][4] * inv, acc[i][5] * inv,
                                acc[i][6] * inv, acc[i][7] * inv);
        float* op = out + (size_t)(b * TT + t0 + row) * QD + (tx << 3);
        *(float4*)(op + 0) = o0;
        *(float4*)(op + 4) = o1;
    }
}

// ---------------------------------------------------------------------------
// Launch
// ---------------------------------------------------------------------------
extern "C" void kernel_launch(void* const* d_in, const int* in_sizes, int n_in,
                              void* d_out, int out_size)
{
    const float* x    = (const float*)d_in[0];
    const void*  mask = d_in[1];                 // dtype detected on device
    const float* Wq   = (const float*)d_in[2];
    const float* Wk   = (const float*)d_in[3];
    const float* Wv   = (const float*)d_in[4];
    float*       out  = (float*)d_out;
    (void)in_sizes; (void)n_in; (void)out_size;

    // Mask canonicalization (dtype sniff + expand to fp32)
    mask_sniff<<<1, 256>>>((const uint8_t*)mask);
    mask_expand<<<(BB * TT + 255) / 256, 256>>>(mask);

    // QKV projections: M tiles = 16384/64 = 256, N tiles = 128/64 = 2, 3 weights
    dim3 g1(256, 2, 3);
    proj_kernel<<<g1, 256>>>(x, Wq, Wk, Wv);

    // Flash attention: 32 query tiles x 8 batches
    cudaFuncSetAttribute(attn_kernel,
                         cudaFuncAttributeMaxDynamicSharedMemorySize,
                         ATTN_SMEM_BYTES);
    dim3 g2(TT / 64, BB);
    attn_kernel<<<g2, 256, ATTN_SMEM_BYTES>>>(out);
}

// round 5
// speedup vs baseline: 1.0005x; 1.0005x over previous
#include <cuda_runtime.h>
#include <cstdint>

// Problem constants
#define BB 8
#define TT 2048
#define DD 1024
#define QD 128
#define NEGV -1000000000.0f

// Scratch for q, k, v projections (8*2048*128 fp32 each = 8 MB each)
__device__ float g_q[BB * TT * QD];
__device__ float g_k[BB * TT * QD];
__device__ float g_v[BB * TT * QD];
// Canonical fp32 mask (1.0 = keep, 0.0 = masked) + detected dtype kind
__device__ float g_mask[BB * TT];
__device__ int   g_mask_kind;   // 0 = int32, 1 = uint8, 2 = float32

// ---------------------------------------------------------------------------
// Mask dtype sniffer: the harness ships jnp.bool_ as one of uint8/int32/f32.
//   int32 one  = 01 00 00 00   -> bytes @+1 always 0, @+3 always 0
//   f32   one  = 00 00 80 3F   -> bytes @+1 always 0, @+3 = 0x3F when set
//   uint8 data = random 0/1 at every byte -> byte @+1 nonzero somewhere
// So: any nonzero byte at offset%4==1 => uint8; else any nonzero at
// offset%4==3 => float32; else int32. Single CTA, reads exactly 16384 bytes
// (the smallest possible size for any of the three interpretations).
// ---------------------------------------------------------------------------
__global__ void mask_sniff(const uint8_t* __restrict__ m)
{
    __shared__ unsigned r1[256], r3[256];
    unsigned o1 = 0, o3 = 0;
    const uint32_t* w = (const uint32_t*)m;
    for (int i = threadIdx.x; i < (BB * TT) / 4; i += 256) {
        uint32_t v = w[i];
        o1 |= (v >> 8)  & 0xFFu;   // byte offset 1
        o3 |= (v >> 24) & 0xFFu;   // byte offset 3
    }
    r1[threadIdx.x] = o1; r3[threadIdx.x] = o3;
    __syncthreads();
    for (int s = 128; s; s >>= 1) {
        if (threadIdx.x < s) {
            r1[threadIdx.x] |= r1[threadIdx.x + s];
            r3[threadIdx.x] |= r3[threadIdx.x + s];
        }
        __syncthreads();
    }
    if (threadIdx.x == 0)
        g_mask_kind = r1[0] ? 1 : (r3[0] ? 2 : 0);
}

__global__ void mask_expand(const void* __restrict__ m)
{
    int s = blockIdx.x * 256 + threadIdx.x;
    if (s >= BB * TT) return;
    int kind = g_mask_kind;
    float v;
    if (kind == 1)      v = ((const uint8_t*)m)[s] ? 1.0f : 0.0f;
    else if (kind == 2) v = (((const float*)m)[s] != 0.0f) ? 1.0f : 0.0f;
    else                v = ((const int*)m)[s] ? 1.0f : 0.0f;
    g_mask[s] = v;
}

// ---------------------------------------------------------------------------
// Kernel 1: fused projection GEMM.
//   out[M=B*T, 128] = x[M, 1024] @ W^T   for W in {Wq, Wk, Wv}
// Tile: 64(M) x 64(N), BK=16, 256 threads, 4x4 per-thread microtile.
// ---------------------------------------------------------------------------
__global__ __launch_bounds__(256) void proj_kernel(
    const float* __restrict__ x,
    const float* __restrict__ Wq,
    const float* __restrict__ Wk,
    const float* __restrict__ Wv)
{
    __shared__ float As[16][64];   // As[k][m]
    __shared__ float Bs[16][64];   // Bs[k][n]

    const int m0 = blockIdx.x * 64;
    const int n0 = blockIdx.y * 64;
    const int z  = blockIdx.z;
    const float* __restrict__ W = (z == 0) ? Wq : ((z == 1) ? Wk : Wv);
    float* __restrict__ outp    = (z == 0) ? g_q : ((z == 1) ? g_k : g_v);

    const int tid  = threadIdx.x;
    const int ty   = tid >> 4;         // 0..15
    const int tx   = tid & 15;         // 0..15
    const int lrow = tid >> 2;         // 0..63
    const int lk   = (tid & 3) << 2;   // 0,4,8,12

    const float* xg = x + (size_t)(m0 + lrow) * DD + lk;
    const float* wg = W + (size_t)(n0 + lrow) * DD + lk;

    float acc[4][4] = {};

    for (int k0 = 0; k0 < DD; k0 += 16) {
        float4 a = *(const float4*)(xg + k0);
        float4 b = *(const float4*)(wg + k0);
        As[lk + 0][lrow] = a.x; As[lk + 1][lrow] = a.y;
        As[lk + 2][lrow] = a.z; As[lk + 3][lrow] = a.w;
        Bs[lk + 0][lrow] = b.x; Bs[lk + 1][lrow] = b.y;
        Bs[lk + 2][lrow] = b.z; Bs[lk + 3][lrow] = b.w;
        __syncthreads();
        #pragma unroll
        for (int kk = 0; kk < 16; kk++) {
            float4 av = *(const float4*)&As[kk][ty << 2];
            float4 bv = *(const float4*)&Bs[kk][tx << 2];
            float aa[4] = {av.x, av.y, av.z, av.w};
            float bb[4] = {bv.x, bv.y, bv.z, bv.w};
            #pragma unroll
            for (int i = 0; i < 4; i++)
                #pragma unroll
                for (int j = 0; j < 4; j++)
                    acc[i][j] = fmaf(aa[i], bb[j], acc[i][j]);
        }
        __syncthreads();
    }

    #pragma unroll
    for (int i = 0; i < 4; i++) {
        float4 v = make_float4(acc[i][0], acc[i][1], acc[i][2], acc[i][3]);
        *(float4*)&outp[(size_t)(m0 + (ty << 2) + i) * QD + n0 + (tx << 2)] = v;
    }
}

// ---------------------------------------------------------------------------
// Kernel 2: flash attention with key-position mask.
// One CTA handles 64 query rows of one batch; loops over all 2048 keys in
// 64-row tiles with online softmax. 256 threads.
// ---------------------------------------------------------------------------
#define ATTN_SMEM_FLOATS (128*64 + 128*64 + 64*128 + 64*64 + 5*64)
#define ATTN_SMEM_BYTES  (ATTN_SMEM_FLOATS * 4)

__global__ __launch_bounds__(256) void attn_kernel(float* __restrict__ out)
{
    extern __shared__ float sm[];
    float* Qs       = sm;                 // [128][64]  Qs[d][q]
    float* Ks       = Qs + 128 * 64;      // [128][64]  Ks[d][s]
    float* Vs       = Ks + 128 * 64;      // [64][128]  Vs[s][d]
    float* Ps       = Vs + 64 * 128;      // [64][64]   Ps[s][q]
    float* sm_m     = Ps + 64 * 64;       // running max  [64]
    float* sm_sum   = sm_m + 64;          // running sum  [64]
    float* sm_scale = sm_sum + 64;        // rescale      [64]
    float* sm_rmax  = sm_scale + 64;      // tile rowmax  [64]
    float* mk       = sm_rmax + 64;       // mask tile    [64]

    const int tid = threadIdx.x;
    const int b   = blockIdx.y;
    const int t0  = blockIdx.x * 64;
    const int ty  = tid >> 4;   // 0..15
    const int tx  = tid & 15;   // 0..15

    // Load Q tile (64 x 128), transposed into Qs[d][q]
    {
        const float* qg = g_q + (size_t)(b * TT + t0) * QD;
        #pragma unroll
        for (int r = 0; r < 8; r++) {
            int idx = tid + r * 256;          // float4 index, 0..2047
            int row = idx >> 5;               // 0..63
            int dq  = (idx & 31) << 2;        // 0..124
            float4 v = *(const float4*)(qg + row * QD + dq);
            Qs[(dq + 0) * 64 + row] = v.x; Qs[(dq + 1) * 64 + row] = v.y;
            Qs[(dq + 2) * 64 + row] = v.z; Qs[(dq + 3) * 64 + row] = v.w;
        }
    }
    if (tid < 64) { sm_m[tid] = -3.0e38f; sm_sum[tid] = 0.0f; }

    float acc[4][8] = {};

    const float* mg = g_mask + b * TT;
    const float* kg = g_k + (size_t)(b * TT) * QD;
    const float* vg = g_v + (size_t)(b * TT) * QD;

    for (int s0 = 0; s0 < TT; s0 += 64) {
        __syncthreads();  // protect smem from previous iteration / Q load
        if (tid < 64) mk[tid] = mg[s0 + tid];
        #pragma unroll
        for (int r = 0; r < 8; r++) {
            int idx = tid + r * 256;
            int row = idx >> 5;
            int dq  = (idx & 31) << 2;
            float4 kv = *(const float4*)(kg + (s0 + row) * QD + dq);
            Ks[(dq + 0) * 64 + row] = kv.x; Ks[(dq + 1) * 64 + row] = kv.y;
            Ks[(dq + 2) * 64 + row] = kv.z; Ks[(dq + 3) * 64 + row] = kv.w;
            float4 vv = *(const float4*)(vg + (s0 + row) * QD + dq);
            *(float4*)&Vs[row * 128 + dq] = vv;
        }
        __syncthreads();

        // GEMM1: logits[4q][4s] = Q . K^T over d=128
        float l[4][4] = {};
        #pragma unroll 8
        for (int d = 0; d < 128; d++) {
            float4 a  = *(const float4*)&Qs[d * 64 + (ty << 2)];
            float4 bq = *(const float4*)&Ks[d * 64 + (tx << 2)];
            float aa[4] = {a.x, a.y, a.z, a.w};
            float bb[4] = {bq.x, bq.y, bq.z, bq.w};
            #pragma unroll
            for (int i = 0; i < 4; i++)
                #pragma unroll
                for (int j = 0; j < 4; j++)
                    l[i][j] = fmaf(aa[i], bb[j], l[i][j]);
        }

        // Mask + per-tile row max
        float mkj[4];
        #pragma unroll
        for (int j = 0; j < 4; j++) mkj[j] = mk[(tx << 2) + j];
        float rm[4];
        #pragma unroll
        for (int i = 0; i < 4; i++) {
            #pragma unroll
            for (int j = 0; j < 4; j++)
                l[i][j] = (mkj[j] != 0.0f) ? l[i][j] : NEGV;
            rm[i] = fmaxf(fmaxf(l[i][0], l[i][1]), fmaxf(l[i][2], l[i][3]));
        }
        #pragma unroll
        for (int i = 0; i < 4; i++) {
            #pragma unroll
            for (int off = 8; off; off >>= 1)
                rm[i] = fmaxf(rm[i], __shfl_xor_sync(0xffffffffu, rm[i], off));
        }
        if (tx == 0) {
            #pragma unroll
            for (int i = 0; i < 4; i++) sm_rmax[(ty << 2) + i] = rm[i];
        }
        __syncthreads();

        // Online softmax state update (one thread per row)
        if (tid < 64) {
            float mo = sm_m[tid];
            float mn = fmaxf(mo, sm_rmax[tid]);
            float sc = __expf(mo - mn);
            sm_scale[tid] = sc;
            sm_m[tid]     = mn;
            sm_sum[tid]  *= sc;
        }
        __syncthreads();

        // p = exp(l - m_new), write Ps[s][q], accumulate row sums
        float rs[4];
        #pragma unroll
        for (int i = 0; i < 4; i++) {
            int row = (ty << 2) + i;
            float mn = sm_m[row];
            float p[4];
            #pragma unroll
            for (int j = 0; j < 4; j++) {
                p[j] = (mkj[j] != 0.0f) ? __expf(l[i][j] - mn) : 0.0f;
                Ps[((tx << 2) + j) * 64 + row] = p[j];
            }
            rs[i] = (p[0] + p[1]) + (p[2] + p[3]);
        }
        #pragma unroll
        for (int i = 0; i < 4; i++) {
            #pragma unroll
            for (int off = 8; off; off >>= 1)
                rs[i] += __shfl_xor_sync(0xffffffffu, rs[i], off);
        }
        if (tx == 0) {
            #pragma unroll
            for (int i = 0; i < 4; i++) sm_sum[(ty << 2) + i] += rs[i];
        }
        // Rescale accumulator (same ty->row mapping as GEMM2)
        #pragma unroll
        for (int i = 0; i < 4; i++) {
            float sc = sm_scale[(ty << 2) + i];
            #pragma unroll
            for (int j = 0; j < 8; j++) acc[i][j] *= sc;
        }
        __syncthreads();  // Ps fully written

        // GEMM2: acc[4q][8d] += P[64q][64s] @ V[64s][128d]
        #pragma unroll 4
        for (int ss = 0; ss < 64; ss++) {
            float4 a  = *(const float4*)&Ps[ss * 64 + (ty << 2)];
            float4 b0 = *(const float4*)&Vs[ss * 128 + (tx << 3)];
            float4 b1 = *(const float4*)&Vs[ss * 128 + (tx << 3) + 4];
            float aa[4] = {a.x, a.y, a.z, a.w};
            float bb[8] = {b0.x, b0.y, b0.z, b0.w, b1.x, b1.y, b1.z, b1.w};
            #pragma unroll
            for (int i = 0; i < 4; i++)
                #pragma unroll
                for (int j = 0; j < 8; j++)
                    acc[i][j] = fmaf(aa[i], bb[j], acc[i][j]);
        }
    }
    __syncthreads();

    // Final normalize + store
    #pragma unroll
    for (int i = 0; i < 4; i++) {
        int row = (ty << 2) + i;
        float inv = 1.0f / sm_sum[row];
        float4 o0 = make_float4(acc[i][0] * inv, acc[i][1] * inv,
                                acc[i][2] * inv, acc[i][3] * inv);
        float4 o1 = make_float4(acc[i][4] * inv, acc[i][5] * inv,
                                acc[i][6] * inv, acc[i][7] * inv);
        float* op = out + (size_t)(b * TT + t0 + row) * QD + (tx << 3);
        *(float4*)(op + 0) = o0;
        *(float4*)(op + 4) = o1;
    }
}

// ---------------------------------------------------------------------------
// Launch
// ---------------------------------------------------------------------------
extern "C" void kernel_launch(void* const* d_in, const int* in_sizes, int n_in,
                              void* d_out, int out_size)
{
    const float* x    = (const float*)d_in[0];
    const void*  mask = d_in[1];                 // dtype detected on device
    const float* Wq   = (const float*)d_in[2];
    const float* Wk   = (const float*)d_in[3];
    const float* Wv   = (const float*)d_in[4];
    float*       out  = (float*)d_out;
    (void)in_sizes; (void)n_in; (void)out_size;

    // Mask canonicalization (dtype sniff + expand to fp32)
    mask_sniff<<<1, 256>>>((const uint8_t*)mask);
    mask_expand<<<(BB * TT + 255) / 256, 256>>>(mask);

    // QKV projections: M tiles = 16384/64 = 256, N tiles = 128/64 = 2, 3 weights
    dim3 g1(256, 2, 3);
    proj_kernel<<<g1, 256>>>(x, Wq, Wk, Wv);

    // Flash attention: 32 query tiles x 8 batches
    cudaFuncSetAttribute(attn_kernel,
                         cudaFuncAttributeMaxDynamicSharedMemorySize,
                         ATTN_SMEM_BYTES);
    dim3 g2(TT / 64, BB);
    attn_kernel<<<g2, 256, ATTN_SMEM_BYTES>>>(out);
}